// round 10
// baseline (speedup 1.0000x reference)
#include <cuda_runtime.h>
#include <cuda_bf16.h>
#include <math.h>
#include <stdint.h>

// Problem constants
#define B_SZ   4
#define L_DOC  1024
#define R_REL  97
#define NHEAD  12
#define HD     64
#define DM     768          // NHEAD * HD
#define M_DOC  (B_SZ * L_DOC)   // 4096
#define M_REL  (B_SZ * R_REL)   // 388
#define SMOOTH 1e-6f
#define LN_EPS 1e-6f
#define ATTN_SCALE 0.125f   // 1/sqrt(64)
#define QT_DOC 16           // 1024/64 doc q-tiles
#define QT_REL 2            // ceil(97/64) rel q-tiles
#define N_CHUNK 16          // L_DOC/64 key chunks

// ---------------- scratch (device globals; no allocation allowed) ----------------
__device__ float g_dq[M_DOC * DM];
__device__ float g_dk[M_DOC * DM];
__device__ float g_dv[M_DOC * DM];
__device__ float g_rk[M_REL * DM];
__device__ float g_rv[M_REL * DM];
__device__ float g_ksum[B_SZ * DM];
__device__ float g_vsum[B_SZ * DM];
__device__ float g_psid[M_DOC * DM];
__device__ float g_psir[M_REL * DM];
__device__ float g_yd[M_DOC * DM];
__device__ float g_yr[M_REL * DM];

// ---------------- SGEMM core: C = A[MxK] @ B[KxN] (+res), row-major ----------------
// BM=BN=128, BK=16, 256 threads, 8x8 per thread, double-buffered smem with
// register-staged global prefetch (one __syncthreads per K-step).
__device__ __forceinline__ void sgemm_body(
    const float* __restrict__ A, const float* __restrict__ B,
    const float* __restrict__ res, float* __restrict__ C,
    int M, int N, int K, int by, int bx)
{
    __shared__ float As[2][16][132];   // transposed A tile: As[buf][k][m]
    __shared__ float Bs[2][16][132];   // Bs[buf][k][n]
    const int tid = threadIdx.x;
    const int tx = tid & 15, ty = tid >> 4;
    const int row0 = by * 128 + ty * 8;
    const int col0 = bx * 128 + tx * 8;

    // per-thread load coordinates (fixed across tiles)
    const int ar0 = tid >> 2;                 // A row within tile (elem 0)
    const int ak0 = (tid & 3) << 2;           // A k within tile   (elem 0)
    const int ar1 = (tid + 256) >> 2;
    const int ak1 = ((tid + 256) & 3) << 2;
    const int bk0 = tid >> 5;                 // B k within tile
    const int bn0 = (tid & 31) << 2;          // B n within tile
    const int bk1 = (tid + 256) >> 5;
    const int bn1 = bn0;                      // same (tid&31) pattern
    const int gra0 = by * 128 + ar0;
    const int gra1 = by * 128 + ar1;
    const int gcb  = bx * 128;

    float4 ra0, ra1, rb0, rb1;

    // prefetch tile 0 into registers
    {
        ra0 = make_float4(0.f, 0.f, 0.f, 0.f);
        ra1 = make_float4(0.f, 0.f, 0.f, 0.f);
        if (gra0 < M) ra0 = *(const float4*)&A[(size_t)gra0 * K + ak0];
        if (gra1 < M) ra1 = *(const float4*)&A[(size_t)gra1 * K + ak1];
        rb0 = *(const float4*)&B[(size_t)bk0 * N + gcb + bn0];
        rb1 = *(const float4*)&B[(size_t)bk1 * N + gcb + bn1];
    }
    // store tile 0 to buffer 0
    As[0][ak0 + 0][ar0] = ra0.x; As[0][ak0 + 1][ar0] = ra0.y;
    As[0][ak0 + 2][ar0] = ra0.z; As[0][ak0 + 3][ar0] = ra0.w;
    As[0][ak1 + 0][ar1] = ra1.x; As[0][ak1 + 1][ar1] = ra1.y;
    As[0][ak1 + 2][ar1] = ra1.z; As[0][ak1 + 3][ar1] = ra1.w;
    *(float4*)&Bs[0][bk0][bn0] = rb0;
    *(float4*)&Bs[0][bk1][bn1] = rb1;
    __syncthreads();

    float acc[8][8];
    #pragma unroll
    for (int i = 0; i < 8; i++)
        #pragma unroll
        for (int j = 0; j < 8; j++) acc[i][j] = 0.f;

    const int nt = K / 16;
    for (int t = 0; t < nt; t++) {
        const int buf = t & 1;
        // prefetch next tile into registers (overlaps with compute below)
        if (t + 1 < nt) {
            const int kt = (t + 1) * 16;
            ra0 = make_float4(0.f, 0.f, 0.f, 0.f);
            ra1 = make_float4(0.f, 0.f, 0.f, 0.f);
            if (gra0 < M) ra0 = *(const float4*)&A[(size_t)gra0 * K + kt + ak0];
            if (gra1 < M) ra1 = *(const float4*)&A[(size_t)gra1 * K + kt + ak1];
            rb0 = *(const float4*)&B[(size_t)(kt + bk0) * N + gcb + bn0];
            rb1 = *(const float4*)&B[(size_t)(kt + bk1) * N + gcb + bn1];
        }

        #pragma unroll
        for (int k = 0; k < 16; k++) {
            float a[8], b[8];
            *(float4*)&a[0] = *(const float4*)&As[buf][k][ty * 8];
            *(float4*)&a[4] = *(const float4*)&As[buf][k][ty * 8 + 4];
            *(float4*)&b[0] = *(const float4*)&Bs[buf][k][tx * 8];
            *(float4*)&b[4] = *(const float4*)&Bs[buf][k][tx * 8 + 4];
            #pragma unroll
            for (int i = 0; i < 8; i++)
                #pragma unroll
                for (int j = 0; j < 8; j++)
                    acc[i][j] += a[i] * b[j];
        }

        if (t + 1 < nt) {
            const int nb = buf ^ 1;
            As[nb][ak0 + 0][ar0] = ra0.x; As[nb][ak0 + 1][ar0] = ra0.y;
            As[nb][ak0 + 2][ar0] = ra0.z; As[nb][ak0 + 3][ar0] = ra0.w;
            As[nb][ak1 + 0][ar1] = ra1.x; As[nb][ak1 + 1][ar1] = ra1.y;
            As[nb][ak1 + 2][ar1] = ra1.z; As[nb][ak1 + 3][ar1] = ra1.w;
            *(float4*)&Bs[nb][bk0][bn0] = rb0;
            *(float4*)&Bs[nb][bk1][bn1] = rb1;
            __syncthreads();
        }
    }

    #pragma unroll
    for (int i = 0; i < 8; i++) {
        int r = row0 + i;
        if (r >= M) break;
        #pragma unroll
        for (int j = 0; j < 8; j += 4) {
            int c = col0 + j;
            float4 v = make_float4(acc[i][j], acc[i][j+1], acc[i][j+2], acc[i][j+3]);
            if (res) {
                float4 rr = *(const float4*)&res[(size_t)r * N + c];
                v.x += rr.x; v.y += rr.y; v.z += rr.z; v.w += rr.w;
            }
            *(float4*)&C[(size_t)r * N + c] = v;
        }
    }
}

// Batched projections: z in [0,5): {doc@wq, doc@wk, doc@wv, rel@wkr, rel@wvr}
__global__ __launch_bounds__(256) void proj_batched(
    const float* __restrict__ doc, const float* __restrict__ rel,
    const float* __restrict__ wq,  const float* __restrict__ wk,
    const float* __restrict__ wv,  const float* __restrict__ wkr,
    const float* __restrict__ wvr,
    float* __restrict__ dq, float* __restrict__ dk, float* __restrict__ dv,
    float* __restrict__ rk, float* __restrict__ rv)
{
    const int z = blockIdx.z;
    const float* A; const float* B; float* C; int M;
    switch (z) {
        case 0: A = doc; B = wq;  C = dq; M = M_DOC; break;
        case 1: A = doc; B = wk;  C = dk; M = M_DOC; break;
        case 2: A = doc; B = wv;  C = dv; M = M_DOC; break;
        case 3: A = rel; B = wkr; C = rk; M = M_REL; break;
        default:A = rel; B = wvr; C = rv; M = M_REL; break;
    }
    if ((int)blockIdx.y * 128 >= M) return;   // uniform early-exit for rel tail
    sgemm_body(A, B, nullptr, C, M, DM, DM, blockIdx.y, blockIdx.x);
}

// Batched output FCs (fused residual): z=0 doc, z=1 rel
__global__ __launch_bounds__(256) void fc_batched(
    const float* __restrict__ psid, const float* __restrict__ psir,
    const float* __restrict__ fcd,  const float* __restrict__ fcr,
    const float* __restrict__ doc,  const float* __restrict__ rel,
    float* __restrict__ yd, float* __restrict__ yr)
{
    const int z = blockIdx.z;
    const float* A   = z ? psir : psid;
    const float* B   = z ? fcr  : fcd;
    const float* res = z ? rel  : doc;
    float*       C   = z ? yr   : yd;
    const int    M   = z ? M_REL : M_DOC;
    if ((int)blockIdx.y * 128 >= M) return;
    sgemm_body(A, B, res, C, M, DM, DM, blockIdx.y, blockIdx.x);
}

// ---------------- relation sums: ksum[b,:] = sum_r rk[b,r,:]; same for rv ----------------
__global__ __launch_bounds__(128) void relsum_kernel(
    const float* __restrict__ rk, const float* __restrict__ rv,
    float* __restrict__ ksum, float* __restrict__ vsum)
{
    const int b = blockIdx.x;
    const int j = blockIdx.y * 128 + threadIdx.x;
    const float* pk = rk + (size_t)b * R_REL * DM + j;
    const float* pv = rv + (size_t)b * R_REL * DM + j;
    float s1 = 0.f, s2 = 0.f;
    int r = 0;
    #pragma unroll 4
    for (; r + 4 <= R_REL; r += 4) {
        float k0 = pk[(size_t)(r + 0) * DM], v0 = pv[(size_t)(r + 0) * DM];
        float k1 = pk[(size_t)(r + 1) * DM], v1 = pv[(size_t)(r + 1) * DM];
        float k2 = pk[(size_t)(r + 2) * DM], v2 = pv[(size_t)(r + 2) * DM];
        float k3 = pk[(size_t)(r + 3) * DM], v3 = pv[(size_t)(r + 3) * DM];
        s1 += (k0 + k1) + (k2 + k3);
        s2 += (v0 + v1) + (v2 + v3);
    }
    for (; r < R_REL; r++) {
        s1 += pk[(size_t)r * DM];
        s2 += pv[(size_t)r * DM];
    }
    ksum[b * DM + j] = s1;
    vsum[b * DM + j] = s2;
}

// ---------------- merged fused flash attention (doc-doc + rel-cross) ----------------
// blockIdx.x < QT_DOC  : doc mode  Q=dq,  Lq=1024, K/V adds = ksum/vsum, out=psid
// blockIdx.x >= QT_DOC : rel mode  Q=rk,  Lq=97,   out_add = rv,         out=psir
// K/V double-buffered in smem with register-staged global prefetch (same hazard
// pattern as sgemm_body: store targets buf^1, sealed by the trailing barrier).
struct AttnSm {
    float Qt[64][68];      // Qt[d][row]
    float Kt[2][64][68];   // Kt[buf][d][key]
    float Vs[2][64][68];   // Vs[buf][key][d]
    float Ps[64][68];      // Ps[row][key]
    float kb[2][64];       // per-key additive bias (SMOOTH or SMOOTH-1e9)
};

__global__ __launch_bounds__(256, 2) void attn_merged(
    const float* __restrict__ dq,    // [B, L_DOC, DM]
    const float* __restrict__ Kd,    // [B, L_DOC, DM]
    const float* __restrict__ Vd,    // [B, L_DOC, DM]
    const float* __restrict__ rkq,   // [B, R_REL, DM] (Q for rel mode)
    const float* __restrict__ rv,    // [B, R_REL, DM] (out_add for rel mode)
    const float* __restrict__ ksum,  // [B, DM]
    const float* __restrict__ vsum,  // [B, DM]
    const int*   __restrict__ mask,  // [B, L_DOC]
    float* __restrict__ psid,        // [B, L_DOC, DM]
    float* __restrict__ psir)        // [B, R_REL, DM]
{
    extern __shared__ char smraw[];
    AttnSm& sm = *reinterpret_cast<AttnSm*>(smraw);

    const bool is_doc = (blockIdx.x < QT_DOC);
    const int qt = is_doc ? blockIdx.x : blockIdx.x - QT_DOC;
    const int h = blockIdx.y, b = blockIdx.z;
    const int tid = threadIdx.x;
    const int tx = tid & 15, ty = tid >> 4;
    const int r0 = ty * 4, c0 = tx * 4;
    const int q0 = qt * 64;

    const float* Q       = is_doc ? dq   : rkq;
    const float* out_add = is_doc ? nullptr : rv;
    float*       Out     = is_doc ? psid : psir;
    const int    Lq      = is_doc ? L_DOC : R_REL;

    // per-thread K/V load coords: d4 is chunk-invariant, j steps by 16
    const int ld_j  = tid >> 4;          // 0..15 (+16 per i)
    const int ld_d4 = (tid & 15) << 2;   // constant per thread

    // fused adds are chunk-invariant; zero in rel mode (unconditional add)
    float4 ka = make_float4(0.f, 0.f, 0.f, 0.f);
    float4 va = make_float4(0.f, 0.f, 0.f, 0.f);
    if (is_doc) {
        ka = *(const float4*)&ksum[b * DM + h * HD + ld_d4];
        va = *(const float4*)&vsum[b * DM + h * HD + ld_d4];
    }

    float4 pk[4], pv[4];
    float  pb = 0.f;

    // ---- prefetch chunk 0 into registers ----
    #pragma unroll
    for (int i = 0; i < 4; i++) {
        size_t gidx = (size_t)(b * L_DOC + ld_j + i * 16) * DM + h * HD + ld_d4;
        pk[i] = *(const float4*)&Kd[gidx];
        pv[i] = *(const float4*)&Vd[gidx];
    }
    if (tid < 64)
        pb = (mask[b * L_DOC + tid] == 0) ? (SMOOTH - 1e9f) : SMOOTH;

    // ---- load Q tile transposed ----
    #pragma unroll
    for (int i = 0; i < 4; i++) {
        int e   = tid + i * 256;
        int row = e >> 4;
        int d4  = (e & 15) << 2;
        int tok = q0 + row;
        float4 v = make_float4(0.f, 0.f, 0.f, 0.f);
        if (tok < Lq)
            v = *(const float4*)&Q[(size_t)(b * Lq + tok) * DM + h * HD + d4];
        sm.Qt[d4 + 0][row] = v.x; sm.Qt[d4 + 1][row] = v.y;
        sm.Qt[d4 + 2][row] = v.z; sm.Qt[d4 + 3][row] = v.w;
    }

    // ---- store chunk 0 to buffer 0 ----
    #pragma unroll
    for (int i = 0; i < 4; i++) {
        int j = ld_j + i * 16;
        sm.Kt[0][ld_d4 + 0][j] = pk[i].x + ka.x;
        sm.Kt[0][ld_d4 + 1][j] = pk[i].y + ka.y;
        sm.Kt[0][ld_d4 + 2][j] = pk[i].z + ka.z;
        sm.Kt[0][ld_d4 + 3][j] = pk[i].w + ka.w;
        float4 vs = make_float4(pv[i].x + va.x, pv[i].y + va.y,
                                pv[i].z + va.z, pv[i].w + va.w);
        *(float4*)&sm.Vs[0][j][ld_d4] = vs;
    }
    if (tid < 64) sm.kb[0][tid] = pb;
    __syncthreads();

    float acc[4][4];
    float m_reg[4], l_reg[4];
    #pragma unroll
    for (int i = 0; i < 4; i++) {
        m_reg[i] = -INFINITY; l_reg[i] = 0.f;
        #pragma unroll
        for (int j = 0; j < 4; j++) acc[i][j] = 0.f;
    }

    for (int t = 0; t < N_CHUNK; t++) {
        const int buf = t & 1;

        // prefetch chunk t+1 into registers (overlaps S-compute + softmax)
        if (t + 1 < N_CHUNK) {
            const int kt = (t + 1) * 64;
            #pragma unroll
            for (int i = 0; i < 4; i++) {
                size_t gidx = (size_t)(b * L_DOC + kt + ld_j + i * 16) * DM + h * HD + ld_d4;
                pk[i] = *(const float4*)&Kd[gidx];
                pv[i] = *(const float4*)&Vd[gidx];
            }
            if (tid < 64)
                pb = (mask[b * L_DOC + kt + tid] == 0) ? (SMOOTH - 1e9f) : SMOOTH;
        }

        // S = Q K^T (4x4 per thread)
        float s[4][4];
        #pragma unroll
        for (int i = 0; i < 4; i++)
            #pragma unroll
            for (int j = 0; j < 4; j++) s[i][j] = 0.f;
        #pragma unroll
        for (int d = 0; d < 64; d++) {
            float4 a  = *(const float4*)&sm.Qt[d][r0];
            float4 bb = *(const float4*)&sm.Kt[buf][d][c0];
            float av[4] = {a.x, a.y, a.z, a.w};
            float bv[4] = {bb.x, bb.y, bb.z, bb.w};
            #pragma unroll
            for (int i = 0; i < 4; i++)
                #pragma unroll
                for (int j = 0; j < 4; j++)
                    s[i][j] += av[i] * bv[j];
        }

        float4 kb4 = *(const float4*)&sm.kb[buf][c0];
        float kb[4] = {kb4.x, kb4.y, kb4.z, kb4.w};

        // scale + bias (mask+smooth folded), row max (shuffle over 16-lane half-warp)
        float mnew[4], f[4];
        #pragma unroll
        for (int i = 0; i < 4; i++) {
            float rm = -INFINITY;
            #pragma unroll
            for (int j = 0; j < 4; j++) {
                float v = fmaf(s[i][j], ATTN_SCALE, kb[j]);
                s[i][j] = v;
                rm = fmaxf(rm, v);
            }
            #pragma unroll
            for (int off = 1; off < 16; off <<= 1)
                rm = fmaxf(rm, __shfl_xor_sync(0xffffffffu, rm, off));
            mnew[i] = fmaxf(m_reg[i], rm);
            f[i] = __expf(m_reg[i] - mnew[i]);   // -inf-finite -> 0 (first chunk)
            m_reg[i] = mnew[i];
        }

        // P = exp(S - m), row sums via shuffle; write P to shared
        #pragma unroll
        for (int i = 0; i < 4; i++) {
            float p0 = __expf(s[i][0] - m_reg[i]);
            float p1 = __expf(s[i][1] - m_reg[i]);
            float p2 = __expf(s[i][2] - m_reg[i]);
            float p3 = __expf(s[i][3] - m_reg[i]);
            float rs = p0 + p1 + p2 + p3;
            #pragma unroll
            for (int off = 1; off < 16; off <<= 1)
                rs += __shfl_xor_sync(0xffffffffu, rs, off);
            l_reg[i] = l_reg[i] * f[i] + rs;
            #pragma unroll
            for (int j = 0; j < 4; j++) acc[i][j] *= f[i];
            *(float4*)&sm.Ps[r0 + i][c0] = make_float4(p0, p1, p2, p3);
        }
        __syncthreads();

        // O += P @ V : keys in groups of 4; P rows read as float4
        #pragma unroll
        for (int j4 = 0; j4 < 64; j4 += 4) {
            float4 p0 = *(const float4*)&sm.Ps[r0 + 0][j4];
            float4 p1 = *(const float4*)&sm.Ps[r0 + 1][j4];
            float4 p2 = *(const float4*)&sm.Ps[r0 + 2][j4];
            float4 p3 = *(const float4*)&sm.Ps[r0 + 3][j4];
            float pr[4][4] = {{p0.x, p0.y, p0.z, p0.w},
                              {p1.x, p1.y, p1.z, p1.w},
                              {p2.x, p2.y, p2.z, p2.w},
                              {p3.x, p3.y, p3.z, p3.w}};
            #pragma unroll
            for (int jj = 0; jj < 4; jj++) {
                float4 vv = *(const float4*)&sm.Vs[buf][j4 + jj][c0];
                float bv[4] = {vv.x, vv.y, vv.z, vv.w};
                #pragma unroll
                for (int i = 0; i < 4; i++) {
                    #pragma unroll
                    for (int c = 0; c < 4; c++)
                        acc[i][c] += pr[i][jj] * bv[c];
                }
            }
        }

        // store prefetched chunk t+1 to the other buffer (read last in t-1, sealed)
        if (t + 1 < N_CHUNK) {
            const int nb = buf ^ 1;
            #pragma unroll
            for (int i = 0; i < 4; i++) {
                int j = ld_j + i * 16;
                sm.Kt[nb][ld_d4 + 0][j] = pk[i].x + ka.x;
                sm.Kt[nb][ld_d4 + 1][j] = pk[i].y + ka.y;
                sm.Kt[nb][ld_d4 + 2][j] = pk[i].z + ka.z;
                sm.Kt[nb][ld_d4 + 3][j] = pk[i].w + ka.w;
                float4 vs = make_float4(pv[i].x + va.x, pv[i].y + va.y,
                                        pv[i].z + va.z, pv[i].w + va.w);
                *(float4*)&sm.Vs[nb][j][ld_d4] = vs;
            }
            if (tid < 64) sm.kb[nb][tid] = pb;
        }
        __syncthreads();
    }

    // epilogue
    #pragma unroll
    for (int i = 0; i < 4; i++) {
        int tok = q0 + r0 + i;
        if (tok >= Lq) continue;
        float inv = 1.0f / l_reg[i];
        size_t oidx = (size_t)(b * Lq + tok) * DM + h * HD + c0;
        float4 o = make_float4(acc[i][0] * inv, acc[i][1] * inv,
                               acc[i][2] * inv, acc[i][3] * inv);
        if (out_add) {
            float4 oa = *(const float4*)&out_add[oidx];
            o.x += oa.x; o.y += oa.y; o.z += oa.z; o.w += oa.w;
        }
        *(float4*)&Out[oidx] = o;
    }
}

// ---------------- merged LayerNorm: rows [0,M_DOC) doc, [M_DOC,M_DOC+M_REL) rel ----------------
// 192 threads: one float4 per thread per array (768 = 192*4). Vectorized LDG/STG.
__global__ __launch_bounds__(192) void ln_merged(
    const float* __restrict__ yd, const float* __restrict__ yr,
    const float* __restrict__ gd, const float* __restrict__ bd,
    const float* __restrict__ gr, const float* __restrict__ br,
    float* __restrict__ out_doc, float* __restrict__ out_rel)
{
    const int rid = blockIdx.x;
    const bool is_doc = (rid < M_DOC);
    const int row = is_doc ? rid : rid - M_DOC;
    const float* y  = is_doc ? yd : yr;
    const float* g  = is_doc ? gd : gr;
    const float* be = is_doc ? bd : br;
    float* out      = is_doc ? out_doc : out_rel;

    const int tid = threadIdx.x;  // 192
    const int lane = tid & 31, wid = tid >> 5;   // 6 warps
    const size_t base = (size_t)row * DM;

    float4 v = *(const float4*)&y[base + tid * 4];
    float s  = (v.x + v.y) + (v.z + v.w);
    float sq = (v.x * v.x + v.y * v.y) + (v.z * v.z + v.w * v.w);

    // intra-warp reduce
    #pragma unroll
    for (int o = 16; o > 0; o >>= 1) {
        s  += __shfl_xor_sync(0xffffffffu, s,  o);
        sq += __shfl_xor_sync(0xffffffffu, sq, o);
    }
    __shared__ float ws[6], wq[6];
    if (lane == 0) { ws[wid] = s; wq[wid] = sq; }
    __syncthreads();
    __shared__ float s_mean, s_rstd;
    if (tid == 0) {
        float ts = 0.f, tq = 0.f;
        #pragma unroll
        for (int w = 0; w < 6; w++) { ts += ws[w]; tq += wq[w]; }
        float m   = ts * (1.0f / DM);
        float var = tq * (1.0f / DM) - m * m;
        s_mean = m;
        s_rstd = rsqrtf(var + LN_EPS);
    }
    __syncthreads();
    float m = s_mean, r = s_rstd;
    float4 gg = *(const float4*)&g[tid * 4];
    float4 bb = *(const float4*)&be[tid * 4];
    float4 o;
    o.x = (v.x - m) * r * gg.x + bb.x;
    o.y = (v.y - m) * r * gg.y + bb.y;
    o.z = (v.z - m) * r * gg.z + bb.z;
    o.w = (v.w - m) * r * gg.w + bb.w;
    *(float4*)&out[base + tid * 4] = o;
}

// ---------------- host ----------------
extern "C" void kernel_launch(void* const* d_in, const int* in_sizes, int n_in,
                              void* d_out, int out_size)
{
    const float* doc    = (const float*)d_in[0];
    const float* rel    = (const float*)d_in[1];
    const int*   mask   = (const int*)  d_in[2];
    const float* wq     = (const float*)d_in[3];
    const float* wk     = (const float*)d_in[4];
    const float* wv     = (const float*)d_in[5];
    const float* wkr    = (const float*)d_in[6];
    const float* wvr    = (const float*)d_in[7];
    const float* fcd    = (const float*)d_in[8];
    const float* fcr    = (const float*)d_in[9];
    const float* lngd   = (const float*)d_in[10];
    const float* lnbd   = (const float*)d_in[11];
    const float* lngr   = (const float*)d_in[12];
    const float* lnbr   = (const float*)d_in[13];

    float* out_doc = (float*)d_out;
    float* out_rel = out_doc + (size_t)M_DOC * DM;

    float *dq, *dk, *dv, *rk, *rv, *ksum, *vsum, *psid, *psir, *yd, *yr;
    cudaGetSymbolAddress((void**)&dq,   g_dq);
    cudaGetSymbolAddress((void**)&dk,   g_dk);
    cudaGetSymbolAddress((void**)&dv,   g_dv);
    cudaGetSymbolAddress((void**)&rk,   g_rk);
    cudaGetSymbolAddress((void**)&rv,   g_rv);
    cudaGetSymbolAddress((void**)&ksum, g_ksum);
    cudaGetSymbolAddress((void**)&vsum, g_vsum);
    cudaGetSymbolAddress((void**)&psid, g_psid);
    cudaGetSymbolAddress((void**)&psir, g_psir);
    cudaGetSymbolAddress((void**)&yd,   g_yd);
    cudaGetSymbolAddress((void**)&yr,   g_yr);

    const int attn_smem = (int)sizeof(AttnSm);
    cudaFuncSetAttribute(attn_merged, cudaFuncAttributeMaxDynamicSharedMemorySize, attn_smem);

    dim3 blk(256);

    // all 5 projections in one launch (z selects {A,W,C,M}); rel tail blocks early-exit
    proj_batched<<<dim3(6, 32, 5), blk>>>(doc, rel, wq, wk, wv, wkr, wvr,
                                          dq, dk, dv, rk, rv);

    // relation sums (parallel over batch x column-chunks)
    relsum_kernel<<<dim3(B_SZ, DM / 128), 128>>>(rk, rv, ksum, vsum);

    // doc-doc + rel-cross attention in one launch (x: 16 doc tiles + 2 rel tiles)
    attn_merged<<<dim3(QT_DOC + QT_REL, NHEAD, B_SZ), blk, attn_smem>>>(
        dq, dk, dv, rk, rv, ksum, vsum, mask, psid, psir);

    // both output FCs (fused residual) in one launch
    fc_batched<<<dim3(6, 32, 2), blk>>>(psid, psir, fcd, fcr, doc, rel, yd, yr);

    // both layernorms in one launch -> outputs (192 threads = 768/4 float4 lanes)
    ln_merged<<<M_DOC + M_REL, 192>>>(yd, yr, lngd, lnbd, lngr, lnbr,
                                      out_doc, out_rel);
}

// round 13
// speedup vs baseline: 1.0397x; 1.0397x over previous
#include <cuda_runtime.h>
#include <cuda_bf16.h>
#include <math.h>
#include <stdint.h>

// Problem constants
#define B_SZ   4
#define L_DOC  1024
#define R_REL  97
#define NHEAD  12
#define HD     64
#define DM     768          // NHEAD * HD
#define M_DOC  (B_SZ * L_DOC)   // 4096
#define M_REL  (B_SZ * R_REL)   // 388
#define SMOOTH 1e-6f
#define LN_EPS 1e-6f
#define ATTN_SCALE 0.125f   // 1/sqrt(64)
#define QT_DOC 16           // 1024/64 doc q-tiles
#define QT_REL 2            // ceil(97/64) rel q-tiles
#define N_CHUNK 16          // L_DOC/64 key chunks

// cp.async 16B: global -> shared, no staging registers
#define CP_ASYNC16(smem_u32, gptr) \
    asm volatile("cp.async.ca.shared.global [%0], [%1], 16;" \
                 :: "r"(smem_u32), "l"(gptr) : "memory")
#define CP_ASYNC_COMMIT() asm volatile("cp.async.commit_group;" ::: "memory")
#define CP_ASYNC_WAIT_ALL() asm volatile("cp.async.wait_group 0;" ::: "memory")

// ---------------- scratch (device globals; no allocation allowed) ----------------
__device__ float g_dq[M_DOC * DM];
__device__ float g_dk[M_DOC * DM];
__device__ float g_dv[M_DOC * DM];
__device__ float g_rk[M_REL * DM];
__device__ float g_rv[M_REL * DM];
__device__ float g_ksum[B_SZ * DM];
__device__ float g_vsum[B_SZ * DM];
__device__ float g_psid[M_DOC * DM];
__device__ float g_psir[M_REL * DM];
__device__ float g_yd[M_DOC * DM];
__device__ float g_yr[M_REL * DM];

// ---------------- SGEMM core: C = A[MxK] @ B[KxN] (+res), row-major ----------------
// BM=BN=128, BK=16, 256 threads, 8x8 per thread. Double-buffered smem:
// A via register staging (needs transpose), B via cp.async (no staging regs).
__device__ __forceinline__ void sgemm_body(
    const float* __restrict__ A, const float* __restrict__ B,
    const float* __restrict__ res, float* __restrict__ C,
    int M, int N, int K, int by, int bx)
{
    __shared__ float As[2][16][132];   // transposed A tile: As[buf][k][m]
    __shared__ float Bs[2][16][132];   // Bs[buf][k][n]
    const int tid = threadIdx.x;
    const int tx = tid & 15, ty = tid >> 4;
    const int row0 = by * 128 + ty * 8;
    const int col0 = bx * 128 + tx * 8;

    // per-thread load coordinates (fixed across tiles)
    const int ar0 = tid >> 2;                 // A row within tile (elem 0)
    const int ak0 = (tid & 3) << 2;           // A k within tile   (elem 0)
    const int ar1 = (tid + 256) >> 2;
    const int ak1 = ((tid + 256) & 3) << 2;
    const int bk0 = tid >> 5;                 // B k within tile
    const int bn0 = (tid & 31) << 2;          // B n within tile
    const int bk1 = (tid + 256) >> 5;
    const int bn1 = bn0;
    const int gra0 = by * 128 + ar0;
    const int gra1 = by * 128 + ar1;
    const int gcb  = bx * 128;

    const uint32_t sb0_base = (uint32_t)__cvta_generic_to_shared(&Bs[0][bk0][bn0]);
    const uint32_t sb1_base = (uint32_t)__cvta_generic_to_shared(&Bs[0][bk1][bn1]);
    const uint32_t buf_stride = (uint32_t)(16 * 132 * sizeof(float));

    float4 ra0, ra1;

    // issue cp.async for B tile 0; load A tile 0 via registers
    CP_ASYNC16(sb0_base, &B[(size_t)bk0 * N + gcb + bn0]);
    CP_ASYNC16(sb1_base, &B[(size_t)bk1 * N + gcb + bn1]);
    CP_ASYNC_COMMIT();
    {
        ra0 = make_float4(0.f, 0.f, 0.f, 0.f);
        ra1 = make_float4(0.f, 0.f, 0.f, 0.f);
        if (gra0 < M) ra0 = *(const float4*)&A[(size_t)gra0 * K + ak0];
        if (gra1 < M) ra1 = *(const float4*)&A[(size_t)gra1 * K + ak1];
    }
    As[0][ak0 + 0][ar0] = ra0.x; As[0][ak0 + 1][ar0] = ra0.y;
    As[0][ak0 + 2][ar0] = ra0.z; As[0][ak0 + 3][ar0] = ra0.w;
    As[0][ak1 + 0][ar1] = ra1.x; As[0][ak1 + 1][ar1] = ra1.y;
    As[0][ak1 + 2][ar1] = ra1.z; As[0][ak1 + 3][ar1] = ra1.w;
    CP_ASYNC_WAIT_ALL();
    __syncthreads();

    float acc[8][8];
    #pragma unroll
    for (int i = 0; i < 8; i++)
        #pragma unroll
        for (int j = 0; j < 8; j++) acc[i][j] = 0.f;

    const int nt = K / 16;
    for (int t = 0; t < nt; t++) {
        const int buf = t & 1;
        // prefetch next tile: B via cp.async into other buffer, A into registers
        if (t + 1 < nt) {
            const int kt = (t + 1) * 16;
            const uint32_t off = (uint32_t)((buf ^ 1)) * buf_stride;
            CP_ASYNC16(sb0_base + off, &B[(size_t)(kt + bk0) * N + gcb + bn0]);
            CP_ASYNC16(sb1_base + off, &B[(size_t)(kt + bk1) * N + gcb + bn1]);
            CP_ASYNC_COMMIT();
            ra0 = make_float4(0.f, 0.f, 0.f, 0.f);
            ra1 = make_float4(0.f, 0.f, 0.f, 0.f);
            if (gra0 < M) ra0 = *(const float4*)&A[(size_t)gra0 * K + kt + ak0];
            if (gra1 < M) ra1 = *(const float4*)&A[(size_t)gra1 * K + kt + ak1];
        }

        #pragma unroll
        for (int k = 0; k < 16; k++) {
            float a[8], b[8];
            *(float4*)&a[0] = *(const float4*)&As[buf][k][ty * 8];
            *(float4*)&a[4] = *(const float4*)&As[buf][k][ty * 8 + 4];
            *(float4*)&b[0] = *(const float4*)&Bs[buf][k][tx * 8];
            *(float4*)&b[4] = *(const float4*)&Bs[buf][k][tx * 8 + 4];
            #pragma unroll
            for (int i = 0; i < 8; i++)
                #pragma unroll
                for (int j = 0; j < 8; j++)
                    acc[i][j] += a[i] * b[j];
        }

        if (t + 1 < nt) {
            const int nb = buf ^ 1;
            As[nb][ak0 + 0][ar0] = ra0.x; As[nb][ak0 + 1][ar0] = ra0.y;
            As[nb][ak0 + 2][ar0] = ra0.z; As[nb][ak0 + 3][ar0] = ra0.w;
            As[nb][ak1 + 0][ar1] = ra1.x; As[nb][ak1 + 1][ar1] = ra1.y;
            As[nb][ak1 + 2][ar1] = ra1.z; As[nb][ak1 + 3][ar1] = ra1.w;
            CP_ASYNC_WAIT_ALL();
            __syncthreads();
        }
    }

    #pragma unroll
    for (int i = 0; i < 8; i++) {
        int r = row0 + i;
        if (r >= M) break;
        #pragma unroll
        for (int j = 0; j < 8; j += 4) {
            int c = col0 + j;
            float4 v = make_float4(acc[i][j], acc[i][j+1], acc[i][j+2], acc[i][j+3]);
            if (res) {
                float4 rr = *(const float4*)&res[(size_t)r * N + c];
                v.x += rr.x; v.y += rr.y; v.z += rr.z; v.w += rr.w;
            }
            *(float4*)&C[(size_t)r * N + c] = v;
        }
    }
}

// Batched projections: z in [0,5): {doc@wq, doc@wk, doc@wv, rel@wkr, rel@wvr}
// (256,2): cap regs at 128 so 2 CTAs/SM fit the register file (R10: 149 regs -> occ 12.5%)
__global__ __launch_bounds__(256, 2) void proj_batched(
    const float* __restrict__ doc, const float* __restrict__ rel,
    const float* __restrict__ wq,  const float* __restrict__ wk,
    const float* __restrict__ wv,  const float* __restrict__ wkr,
    const float* __restrict__ wvr,
    float* __restrict__ dq, float* __restrict__ dk, float* __restrict__ dv,
    float* __restrict__ rk, float* __restrict__ rv)
{
    const int z = blockIdx.z;
    const float* A; const float* B; float* C; int M;
    switch (z) {
        case 0: A = doc; B = wq;  C = dq; M = M_DOC; break;
        case 1: A = doc; B = wk;  C = dk; M = M_DOC; break;
        case 2: A = doc; B = wv;  C = dv; M = M_DOC; break;
        case 3: A = rel; B = wkr; C = rk; M = M_REL; break;
        default:A = rel; B = wvr; C = rv; M = M_REL; break;
    }
    if ((int)blockIdx.y * 128 >= M) return;   // uniform early-exit for rel tail
    sgemm_body(A, B, nullptr, C, M, DM, DM, blockIdx.y, blockIdx.x);
}

// Batched output FCs (fused residual): z=0 doc, z=1 rel
__global__ __launch_bounds__(256, 2) void fc_batched(
    const float* __restrict__ psid, const float* __restrict__ psir,
    const float* __restrict__ fcd,  const float* __restrict__ fcr,
    const float* __restrict__ doc,  const float* __restrict__ rel,
    float* __restrict__ yd, float* __restrict__ yr)
{
    const int z = blockIdx.z;
    const float* A   = z ? psir : psid;
    const float* B   = z ? fcr  : fcd;
    const float* res = z ? rel  : doc;
    float*       C   = z ? yr   : yd;
    const int    M   = z ? M_REL : M_DOC;
    if ((int)blockIdx.y * 128 >= M) return;
    sgemm_body(A, B, res, C, M, DM, DM, blockIdx.y, blockIdx.x);
}

// ---------------- relation sums: ksum[b,:] = sum_r rk[b,r,:]; same for rv ----------------
__global__ __launch_bounds__(128) void relsum_kernel(
    const float* __restrict__ rk, const float* __restrict__ rv,
    float* __restrict__ ksum, float* __restrict__ vsum)
{
    const int b = blockIdx.x;
    const int j = blockIdx.y * 128 + threadIdx.x;
    const float* pk = rk + (size_t)b * R_REL * DM + j;
    const float* pv = rv + (size_t)b * R_REL * DM + j;
    float s1 = 0.f, s2 = 0.f;
    int r = 0;
    #pragma unroll 4
    for (; r + 4 <= R_REL; r += 4) {
        float k0 = pk[(size_t)(r + 0) * DM], v0 = pv[(size_t)(r + 0) * DM];
        float k1 = pk[(size_t)(r + 1) * DM], v1 = pv[(size_t)(r + 1) * DM];
        float k2 = pk[(size_t)(r + 2) * DM], v2 = pv[(size_t)(r + 2) * DM];
        float k3 = pk[(size_t)(r + 3) * DM], v3 = pv[(size_t)(r + 3) * DM];
        s1 += (k0 + k1) + (k2 + k3);
        s2 += (v0 + v1) + (v2 + v3);
    }
    for (; r < R_REL; r++) {
        s1 += pk[(size_t)r * DM];
        s2 += pv[(size_t)r * DM];
    }
    ksum[b * DM + j] = s1;
    vsum[b * DM + j] = s2;
}

// ---------------- merged fused flash attention (doc-doc + rel-cross) ----------------
// blockIdx.x < QT_DOC  : doc mode  Q=dq,  Lq=1024, K/V adds = ksum/vsum, out=psid
// blockIdx.x >= QT_DOC : rel mode  Q=rk,  Lq=97,   out_add = rv,         out=psir
// K/V double-buffered in smem with register-staged global prefetch.
struct AttnSm {
    float Qt[64][68];      // Qt[d][row]
    float Kt[2][64][68];   // Kt[buf][d][key]
    float Vs[2][64][68];   // Vs[buf][key][d]
    float Ps[64][68];      // Ps[row][key]
    float kb[2][64];       // per-key additive bias (SMOOTH or SMOOTH-1e9)
};

__global__ __launch_bounds__(256, 2) void attn_merged(
    const float* __restrict__ dq,    // [B, L_DOC, DM]
    const float* __restrict__ Kd,    // [B, L_DOC, DM]
    const float* __restrict__ Vd,    // [B, L_DOC, DM]
    const float* __restrict__ rkq,   // [B, R_REL, DM] (Q for rel mode)
    const float* __restrict__ rv,    // [B, R_REL, DM] (out_add for rel mode)
    const float* __restrict__ ksum,  // [B, DM]
    const float* __restrict__ vsum,  // [B, DM]
    const int*   __restrict__ mask,  // [B, L_DOC]
    float* __restrict__ psid,        // [B, L_DOC, DM]
    float* __restrict__ psir)        // [B, R_REL, DM]
{
    extern __shared__ char smraw[];
    AttnSm& sm = *reinterpret_cast<AttnSm*>(smraw);

    const bool is_doc = (blockIdx.x < QT_DOC);
    const int qt = is_doc ? blockIdx.x : blockIdx.x - QT_DOC;
    const int h = blockIdx.y, b = blockIdx.z;
    const int tid = threadIdx.x;
    const int tx = tid & 15, ty = tid >> 4;
    const int r0 = ty * 4, c0 = tx * 4;
    const int q0 = qt * 64;

    const float* Q       = is_doc ? dq   : rkq;
    const float* out_add = is_doc ? nullptr : rv;
    float*       Out     = is_doc ? psid : psir;
    const int    Lq      = is_doc ? L_DOC : R_REL;

    // per-thread K/V load coords: d4 is chunk-invariant, j steps by 16
    const int ld_j  = tid >> 4;          // 0..15 (+16 per i)
    const int ld_d4 = (tid & 15) << 2;   // constant per thread

    // fused adds are chunk-invariant; zero in rel mode (unconditional add)
    float4 ka = make_float4(0.f, 0.f, 0.f, 0.f);
    float4 va = make_float4(0.f, 0.f, 0.f, 0.f);
    if (is_doc) {
        ka = *(const float4*)&ksum[b * DM + h * HD + ld_d4];
        va = *(const float4*)&vsum[b * DM + h * HD + ld_d4];
    }

    float4 pk[4], pv[4];
    float  pb = 0.f;

    // ---- prefetch chunk 0 into registers ----
    #pragma unroll
    for (int i = 0; i < 4; i++) {
        size_t gidx = (size_t)(b * L_DOC + ld_j + i * 16) * DM + h * HD + ld_d4;
        pk[i] = *(const float4*)&Kd[gidx];
        pv[i] = *(const float4*)&Vd[gidx];
    }
    if (tid < 64)
        pb = (mask[b * L_DOC + tid] == 0) ? (SMOOTH - 1e9f) : SMOOTH;

    // ---- load Q tile transposed ----
    #pragma unroll
    for (int i = 0; i < 4; i++) {
        int e   = tid + i * 256;
        int row = e >> 4;
        int d4  = (e & 15) << 2;
        int tok = q0 + row;
        float4 v = make_float4(0.f, 0.f, 0.f, 0.f);
        if (tok < Lq)
            v = *(const float4*)&Q[(size_t)(b * Lq + tok) * DM + h * HD + d4];
        sm.Qt[d4 + 0][row] = v.x; sm.Qt[d4 + 1][row] = v.y;
        sm.Qt[d4 + 2][row] = v.z; sm.Qt[d4 + 3][row] = v.w;
    }

    // ---- store chunk 0 to buffer 0 ----
    #pragma unroll
    for (int i = 0; i < 4; i++) {
        int j = ld_j + i * 16;
        sm.Kt[0][ld_d4 + 0][j] = pk[i].x + ka.x;
        sm.Kt[0][ld_d4 + 1][j] = pk[i].y + ka.y;
        sm.Kt[0][ld_d4 + 2][j] = pk[i].z + ka.z;
        sm.Kt[0][ld_d4 + 3][j] = pk[i].w + ka.w;
        float4 vs = make_float4(pv[i].x + va.x, pv[i].y + va.y,
                                pv[i].z + va.z, pv[i].w + va.w);
        *(float4*)&sm.Vs[0][j][ld_d4] = vs;
    }
    if (tid < 64) sm.kb[0][tid] = pb;
    __syncthreads();

    float acc[4][4];
    float m_reg[4], l_reg[4];
    #pragma unroll
    for (int i = 0; i < 4; i++) {
        m_reg[i] = -INFINITY; l_reg[i] = 0.f;
        #pragma unroll
        for (int j = 0; j < 4; j++) acc[i][j] = 0.f;
    }

    for (int t = 0; t < N_CHUNK; t++) {
        const int buf = t & 1;

        // prefetch chunk t+1 into registers (overlaps S-compute + softmax)
        if (t + 1 < N_CHUNK) {
            const int kt = (t + 1) * 64;
            #pragma unroll
            for (int i = 0; i < 4; i++) {
                size_t gidx = (size_t)(b * L_DOC + kt + ld_j + i * 16) * DM + h * HD + ld_d4;
                pk[i] = *(const float4*)&Kd[gidx];
                pv[i] = *(const float4*)&Vd[gidx];
            }
            if (tid < 64)
                pb = (mask[b * L_DOC + kt + tid] == 0) ? (SMOOTH - 1e9f) : SMOOTH;
        }

        // S = Q K^T (4x4 per thread)
        float s[4][4];
        #pragma unroll
        for (int i = 0; i < 4; i++)
            #pragma unroll
            for (int j = 0; j < 4; j++) s[i][j] = 0.f;
        #pragma unroll
        for (int d = 0; d < 64; d++) {
            float4 a  = *(const float4*)&sm.Qt[d][r0];
            float4 bb = *(const float4*)&sm.Kt[buf][d][c0];
            float av[4] = {a.x, a.y, a.z, a.w};
            float bv[4] = {bb.x, bb.y, bb.z, bb.w};
            #pragma unroll
            for (int i = 0; i < 4; i++)
                #pragma unroll
                for (int j = 0; j < 4; j++)
                    s[i][j] += av[i] * bv[j];
        }

        float4 kb4 = *(const float4*)&sm.kb[buf][c0];
        float kb[4] = {kb4.x, kb4.y, kb4.z, kb4.w};

        // scale + bias (mask+smooth folded), row max (shuffle over 16-lane half-warp)
        float mnew[4], f[4];
        #pragma unroll
        for (int i = 0; i < 4; i++) {
            float rm = -INFINITY;
            #pragma unroll
            for (int j = 0; j < 4; j++) {
                float v = fmaf(s[i][j], ATTN_SCALE, kb[j]);
                s[i][j] = v;
                rm = fmaxf(rm, v);
            }
            #pragma unroll
            for (int off = 1; off < 16; off <<= 1)
                rm = fmaxf(rm, __shfl_xor_sync(0xffffffffu, rm, off));
            mnew[i] = fmaxf(m_reg[i], rm);
            f[i] = __expf(m_reg[i] - mnew[i]);   // -inf-finite -> 0 (first chunk)
            m_reg[i] = mnew[i];
        }

        // P = exp(S - m), row sums via shuffle; write P to shared
        #pragma unroll
        for (int i = 0; i < 4; i++) {
            float p0 = __expf(s[i][0] - m_reg[i]);
            float p1 = __expf(s[i][1] - m_reg[i]);
            float p2 = __expf(s[i][2] - m_reg[i]);
            float p3 = __expf(s[i][3] - m_reg[i]);
            float rs = p0 + p1 + p2 + p3;
            #pragma unroll
            for (int off = 1; off < 16; off <<= 1)
                rs += __shfl_xor_sync(0xffffffffu, rs, off);
            l_reg[i] = l_reg[i] * f[i] + rs;
            #pragma unroll
            for (int j = 0; j < 4; j++) acc[i][j] *= f[i];
            *(float4*)&sm.Ps[r0 + i][c0] = make_float4(p0, p1, p2, p3);
        }
        __syncthreads();

        // O += P @ V : keys in groups of 4; P rows read as float4
        #pragma unroll
        for (int j4 = 0; j4 < 64; j4 += 4) {
            float4 p0 = *(const float4*)&sm.Ps[r0 + 0][j4];
            float4 p1 = *(const float4*)&sm.Ps[r0 + 1][j4];
            float4 p2 = *(const float4*)&sm.Ps[r0 + 2][j4];
            float4 p3 = *(const float4*)&sm.Ps[r0 + 3][j4];
            float pr[4][4] = {{p0.x, p0.y, p0.z, p0.w},
                              {p1.x, p1.y, p1.z, p1.w},
                              {p2.x, p2.y, p2.z, p2.w},
                              {p3.x, p3.y, p3.z, p3.w}};
            #pragma unroll
            for (int jj = 0; jj < 4; jj++) {
                float4 vv = *(const float4*)&sm.Vs[buf][j4 + jj][c0];
                float bv[4] = {vv.x, vv.y, vv.z, vv.w};
                #pragma unroll
                for (int i = 0; i < 4; i++) {
                    #pragma unroll
                    for (int c = 0; c < 4; c++)
                        acc[i][c] += pr[i][jj] * bv[c];
                }
            }
        }

        // store prefetched chunk t+1 to the other buffer (read last in t-1, sealed)
        if (t + 1 < N_CHUNK) {
            const int nb = buf ^ 1;
            #pragma unroll
            for (int i = 0; i < 4; i++) {
                int j = ld_j + i * 16;
                sm.Kt[nb][ld_d4 + 0][j] = pk[i].x + ka.x;
                sm.Kt[nb][ld_d4 + 1][j] = pk[i].y + ka.y;
                sm.Kt[nb][ld_d4 + 2][j] = pk[i].z + ka.z;
                sm.Kt[nb][ld_d4 + 3][j] = pk[i].w + ka.w;
                float4 vs = make_float4(pv[i].x + va.x, pv[i].y + va.y,
                                        pv[i].z + va.z, pv[i].w + va.w);
                *(float4*)&sm.Vs[nb][j][ld_d4] = vs;
            }
            if (tid < 64) sm.kb[nb][tid] = pb;
        }
        __syncthreads();
    }

    // epilogue
    #pragma unroll
    for (int i = 0; i < 4; i++) {
        int tok = q0 + r0 + i;
        if (tok >= Lq) continue;
        float inv = 1.0f / l_reg[i];
        size_t oidx = (size_t)(b * Lq + tok) * DM + h * HD + c0;
        float4 o = make_float4(acc[i][0] * inv, acc[i][1] * inv,
                               acc[i][2] * inv, acc[i][3] * inv);
        if (out_add) {
            float4 oa = *(const float4*)&out_add[oidx];
            o.x += oa.x; o.y += oa.y; o.z += oa.z; o.w += oa.w;
        }
        *(float4*)&Out[oidx] = o;
    }
}

// ---------------- merged LayerNorm: rows [0,M_DOC) doc, [M_DOC,M_DOC+M_REL) rel ----------------
// 192 threads: one float4 per thread per array (768 = 192*4). Vectorized LDG/STG.
__global__ __launch_bounds__(192) void ln_merged(
    const float* __restrict__ yd, const float* __restrict__ yr,
    const float* __restrict__ gd, const float* __restrict__ bd,
    const float* __restrict__ gr, const float* __restrict__ br,
    float* __restrict__ out_doc, float* __restrict__ out_rel)
{
    const int rid = blockIdx.x;
    const bool is_doc = (rid < M_DOC);
    const int row = is_doc ? rid : rid - M_DOC;
    const float* y  = is_doc ? yd : yr;
    const float* g  = is_doc ? gd : gr;
    const float* be = is_doc ? bd : br;
    float* out      = is_doc ? out_doc : out_rel;

    const int tid = threadIdx.x;  // 192
    const int lane = tid & 31, wid = tid >> 5;   // 6 warps
    const size_t base = (size_t)row * DM;

    float4 v = *(const float4*)&y[base + tid * 4];
    float s  = (v.x + v.y) + (v.z + v.w);
    float sq = (v.x * v.x + v.y * v.y) + (v.z * v.z + v.w * v.w);

    // intra-warp reduce
    #pragma unroll
    for (int o = 16; o > 0; o >>= 1) {
        s  += __shfl_xor_sync(0xffffffffu, s,  o);
        sq += __shfl_xor_sync(0xffffffffu, sq, o);
    }
    __shared__ float ws[6], wq[6];
    if (lane == 0) { ws[wid] = s; wq[wid] = sq; }
    __syncthreads();
    __shared__ float s_mean, s_rstd;
    if (tid == 0) {
        float ts = 0.f, tq = 0.f;
        #pragma unroll
        for (int w = 0; w < 6; w++) { ts += ws[w]; tq += wq[w]; }
        float m   = ts * (1.0f / DM);
        float var = tq * (1.0f / DM) - m * m;
        s_mean = m;
        s_rstd = rsqrtf(var + LN_EPS);
    }
    __syncthreads();
    float m = s_mean, r = s_rstd;
    float4 gg = *(const float4*)&g[tid * 4];
    float4 bb = *(const float4*)&be[tid * 4];
    float4 o;
    o.x = (v.x - m) * r * gg.x + bb.x;
    o.y = (v.y - m) * r * gg.y + bb.y;
    o.z = (v.z - m) * r * gg.z + bb.z;
    o.w = (v.w - m) * r * gg.w + bb.w;
    *(float4*)&out[base + tid * 4] = o;
}

// ---------------- host ----------------
extern "C" void kernel_launch(void* const* d_in, const int* in_sizes, int n_in,
                              void* d_out, int out_size)
{
    const float* doc    = (const float*)d_in[0];
    const float* rel    = (const float*)d_in[1];
    const int*   mask   = (const int*)  d_in[2];
    const float* wq     = (const float*)d_in[3];
    const float* wk     = (const float*)d_in[4];
    const float* wv     = (const float*)d_in[5];
    const float* wkr    = (const float*)d_in[6];
    const float* wvr    = (const float*)d_in[7];
    const float* fcd    = (const float*)d_in[8];
    const float* fcr    = (const float*)d_in[9];
    const float* lngd   = (const float*)d_in[10];
    const float* lnbd   = (const float*)d_in[11];
    const float* lngr   = (const float*)d_in[12];
    const float* lnbr   = (const float*)d_in[13];

    float* out_doc = (float*)d_out;
    float* out_rel = out_doc + (size_t)M_DOC * DM;

    float *dq, *dk, *dv, *rk, *rv, *ksum, *vsum, *psid, *psir, *yd, *yr;
    cudaGetSymbolAddress((void**)&dq,   g_dq);
    cudaGetSymbolAddress((void**)&dk,   g_dk);
    cudaGetSymbolAddress((void**)&dv,   g_dv);
    cudaGetSymbolAddress((void**)&rk,   g_rk);
    cudaGetSymbolAddress((void**)&rv,   g_rv);
    cudaGetSymbolAddress((void**)&ksum, g_ksum);
    cudaGetSymbolAddress((void**)&vsum, g_vsum);
    cudaGetSymbolAddress((void**)&psid, g_psid);
    cudaGetSymbolAddress((void**)&psir, g_psir);
    cudaGetSymbolAddress((void**)&yd,   g_yd);
    cudaGetSymbolAddress((void**)&yr,   g_yr);

    const int attn_smem = (int)sizeof(AttnSm);
    cudaFuncSetAttribute(attn_merged, cudaFuncAttributeMaxDynamicSharedMemorySize, attn_smem);

    dim3 blk(256);

    // all 5 projections in one launch (z selects {A,W,C,M}); rel tail blocks early-exit
    proj_batched<<<dim3(6, 32, 5), blk>>>(doc, rel, wq, wk, wv, wkr, wvr,
                                          dq, dk, dv, rk, rv);

    // relation sums (parallel over batch x column-chunks)
    relsum_kernel<<<dim3(B_SZ, DM / 128), 128>>>(rk, rv, ksum, vsum);

    // doc-doc + rel-cross attention in one launch (x: 16 doc tiles + 2 rel tiles)
    attn_merged<<<dim3(QT_DOC + QT_REL, NHEAD, B_SZ), blk, attn_smem>>>(
        dq, dk, dv, rk, rv, ksum, vsum, mask, psid, psir);

    // both output FCs (fused residual) in one launch
    fc_batched<<<dim3(6, 32, 2), blk>>>(psid, psir, fcd, fcr, doc, rel, yd, yr);

    // both layernorms in one launch -> outputs (192 threads = 768/4 float4 lanes)
    ln_merged<<<M_DOC + M_REL, 192>>>(yd, yr, lngd, lnbd, lngr, lnbr,
                                      out_doc, out_rel);
}

// round 16
// speedup vs baseline: 1.1325x; 1.0893x over previous
#include <cuda_runtime.h>
#include <cuda_bf16.h>
#include <math.h>
#include <stdint.h>

// Problem constants
#define B_SZ   4
#define L_DOC  1024
#define R_REL  97
#define NHEAD  12
#define HD     64
#define DM     768          // NHEAD * HD
#define M_DOC  (B_SZ * L_DOC)   // 4096
#define M_REL  (B_SZ * R_REL)   // 388
#define SMOOTH 1e-6f
#define LN_EPS 1e-6f
#define ATTN_SCALE 0.125f   // 1/sqrt(64)
#define QT_DOC 16           // 1024/64 doc q-tiles
#define QT_REL 2            // ceil(97/64) rel q-tiles
#define N_CHUNK 16          // L_DOC/64 key chunks

// cp.async 16B: global -> shared, no staging registers
#define CP_ASYNC16(smem_u32, gptr) \
    asm volatile("cp.async.ca.shared.global [%0], [%1], 16;" \
                 :: "r"(smem_u32), "l"(gptr) : "memory")
#define CP_ASYNC_COMMIT() asm volatile("cp.async.commit_group;" ::: "memory")
#define CP_ASYNC_WAIT_ALL() asm volatile("cp.async.wait_group 0;" ::: "memory")

// ---------------- scratch (device globals; no allocation allowed) ----------------
__device__ float g_dq[M_DOC * DM];
__device__ float g_dk[M_DOC * DM];
__device__ float g_dv[M_DOC * DM];
__device__ float g_rk[M_REL * DM];
__device__ float g_rv[M_REL * DM];
__device__ float g_ksum[B_SZ * DM];
__device__ float g_vsum[B_SZ * DM];
__device__ float g_psid[M_DOC * DM];
__device__ float g_psir[M_REL * DM];
__device__ float g_yd[M_DOC * DM];
__device__ float g_yr[M_REL * DM];

// ---------------- SGEMM core: C = A[MxK] @ B[KxN] (+res), row-major ----------------
// BM=128, BN=64, BK=16, 256 threads, 8x4 per thread, double-buffered smem.
// A via register staging (needs transpose), B via cp.async (no staging regs).
// Small tile (vs 128x128) cuts regs to ~80 -> 3 CTA/SM (6 warps/SMSP) and
// halves wave quantization loss.
__device__ __forceinline__ void sgemm_body(
    const float* __restrict__ A, const float* __restrict__ B,
    const float* __restrict__ res, float* __restrict__ C,
    int M, int N, int K, int by, int bx)
{
    __shared__ float As[2][16][132];   // transposed A tile: As[buf][k][m]
    __shared__ float Bs[2][16][68];    // Bs[buf][k][n], 64 + 4 pad
    const int tid = threadIdx.x;
    const int tx = tid & 15, ty = tid >> 4;
    const int row0 = by * 128 + ty * 8;
    const int col0 = bx * 64 + tx * 4;

    // A load coords: 128 rows x 16 k = 512 float4, 2 per thread
    const int ar0 = tid >> 2;                 // 0..63
    const int ak0 = (tid & 3) << 2;           // 0,4,8,12
    const int ar1 = (tid + 256) >> 2;         // 64..127
    const int ak1 = ak0;
    // B load coords: 16 k x 64 n = 256 float4, 1 per thread
    const int bk0 = tid >> 4;                 // 0..15
    const int bn0 = (tid & 15) << 2;          // 0..60
    const int gra0 = by * 128 + ar0;
    const int gra1 = by * 128 + ar1;
    const int gcb  = bx * 64;

    const uint32_t sb_base = (uint32_t)__cvta_generic_to_shared(&Bs[0][bk0][bn0]);
    const uint32_t buf_stride = (uint32_t)(16 * 68 * sizeof(float));

    float4 ra0, ra1;

    // tile 0: B via cp.async, A via registers
    CP_ASYNC16(sb_base, &B[(size_t)bk0 * N + gcb + bn0]);
    CP_ASYNC_COMMIT();
    ra0 = make_float4(0.f, 0.f, 0.f, 0.f);
    ra1 = make_float4(0.f, 0.f, 0.f, 0.f);
    if (gra0 < M) ra0 = *(const float4*)&A[(size_t)gra0 * K + ak0];
    if (gra1 < M) ra1 = *(const float4*)&A[(size_t)gra1 * K + ak1];
    As[0][ak0 + 0][ar0] = ra0.x; As[0][ak0 + 1][ar0] = ra0.y;
    As[0][ak0 + 2][ar0] = ra0.z; As[0][ak0 + 3][ar0] = ra0.w;
    As[0][ak1 + 0][ar1] = ra1.x; As[0][ak1 + 1][ar1] = ra1.y;
    As[0][ak1 + 2][ar1] = ra1.z; As[0][ak1 + 3][ar1] = ra1.w;
    CP_ASYNC_WAIT_ALL();
    __syncthreads();

    float acc[8][4];
    #pragma unroll
    for (int i = 0; i < 8; i++)
        #pragma unroll
        for (int j = 0; j < 4; j++) acc[i][j] = 0.f;

    const int nt = K / 16;
    for (int t = 0; t < nt; t++) {
        const int buf = t & 1;
        if (t + 1 < nt) {
            const int kt = (t + 1) * 16;
            const uint32_t off = (uint32_t)(buf ^ 1) * buf_stride;
            CP_ASYNC16(sb_base + off, &B[(size_t)(kt + bk0) * N + gcb + bn0]);
            CP_ASYNC_COMMIT();
            ra0 = make_float4(0.f, 0.f, 0.f, 0.f);
            ra1 = make_float4(0.f, 0.f, 0.f, 0.f);
            if (gra0 < M) ra0 = *(const float4*)&A[(size_t)gra0 * K + kt + ak0];
            if (gra1 < M) ra1 = *(const float4*)&A[(size_t)gra1 * K + kt + ak1];
        }

        #pragma unroll
        for (int k = 0; k < 16; k++) {
            float a[8];
            *(float4*)&a[0] = *(const float4*)&As[buf][k][ty * 8];
            *(float4*)&a[4] = *(const float4*)&As[buf][k][ty * 8 + 4];
            float4 b4 = *(const float4*)&Bs[buf][k][tx * 4];
            float b[4] = {b4.x, b4.y, b4.z, b4.w};
            #pragma unroll
            for (int i = 0; i < 8; i++)
                #pragma unroll
                for (int j = 0; j < 4; j++)
                    acc[i][j] += a[i] * b[j];
        }

        if (t + 1 < nt) {
            const int nb = buf ^ 1;
            As[nb][ak0 + 0][ar0] = ra0.x; As[nb][ak0 + 1][ar0] = ra0.y;
            As[nb][ak0 + 2][ar0] = ra0.z; As[nb][ak0 + 3][ar0] = ra0.w;
            As[nb][ak1 + 0][ar1] = ra1.x; As[nb][ak1 + 1][ar1] = ra1.y;
            As[nb][ak1 + 2][ar1] = ra1.z; As[nb][ak1 + 3][ar1] = ra1.w;
            CP_ASYNC_WAIT_ALL();
            __syncthreads();
        }
    }

    #pragma unroll
    for (int i = 0; i < 8; i++) {
        int r = row0 + i;
        if (r >= M) break;
        float4 v = make_float4(acc[i][0], acc[i][1], acc[i][2], acc[i][3]);
        if (res) {
            float4 rr = *(const float4*)&res[(size_t)r * N + col0];
            v.x += rr.x; v.y += rr.y; v.z += rr.z; v.w += rr.w;
        }
        *(float4*)&C[(size_t)r * N + col0] = v;
    }
}

// Batched projections: z in [0,5): {doc@wq, doc@wk, doc@wv, rel@wkr, rel@wvr}
// (256,3): ~85-reg cap -> 3 CTA/SM (R13 evidence: occupancy is the GEMM limiter)
__global__ __launch_bounds__(256, 3) void proj_batched(
    const float* __restrict__ doc, const float* __restrict__ rel,
    const float* __restrict__ wq,  const float* __restrict__ wk,
    const float* __restrict__ wv,  const float* __restrict__ wkr,
    const float* __restrict__ wvr,
    float* __restrict__ dq, float* __restrict__ dk, float* __restrict__ dv,
    float* __restrict__ rk, float* __restrict__ rv)
{
    const int z = blockIdx.z;
    const float* A; const float* B; float* C; int M;
    switch (z) {
        case 0: A = doc; B = wq;  C = dq; M = M_DOC; break;
        case 1: A = doc; B = wk;  C = dk; M = M_DOC; break;
        case 2: A = doc; B = wv;  C = dv; M = M_DOC; break;
        case 3: A = rel; B = wkr; C = rk; M = M_REL; break;
        default:A = rel; B = wvr; C = rv; M = M_REL; break;
    }
    if ((int)blockIdx.y * 128 >= M) return;   // uniform early-exit for rel tail
    sgemm_body(A, B, nullptr, C, M, DM, DM, blockIdx.y, blockIdx.x);
}

// Batched output FCs (fused residual): z=0 doc, z=1 rel
__global__ __launch_bounds__(256, 3) void fc_batched(
    const float* __restrict__ psid, const float* __restrict__ psir,
    const float* __restrict__ fcd,  const float* __restrict__ fcr,
    const float* __restrict__ doc,  const float* __restrict__ rel,
    float* __restrict__ yd, float* __restrict__ yr)
{
    const int z = blockIdx.z;
    const float* A   = z ? psir : psid;
    const float* B   = z ? fcr  : fcd;
    const float* res = z ? rel  : doc;
    float*       C   = z ? yr   : yd;
    const int    M   = z ? M_REL : M_DOC;
    if ((int)blockIdx.y * 128 >= M) return;
    sgemm_body(A, B, res, C, M, DM, DM, blockIdx.y, blockIdx.x);
}

// ---------------- relation sums: ksum[b,:] = sum_r rk[b,r,:]; same for rv ----------------
__global__ __launch_bounds__(128) void relsum_kernel(
    const float* __restrict__ rk, const float* __restrict__ rv,
    float* __restrict__ ksum, float* __restrict__ vsum)
{
    const int b = blockIdx.x;
    const int j = blockIdx.y * 128 + threadIdx.x;
    const float* pk = rk + (size_t)b * R_REL * DM + j;
    const float* pv = rv + (size_t)b * R_REL * DM + j;
    float s1 = 0.f, s2 = 0.f;
    int r = 0;
    #pragma unroll 4
    for (; r + 4 <= R_REL; r += 4) {
        float k0 = pk[(size_t)(r + 0) * DM], v0 = pv[(size_t)(r + 0) * DM];
        float k1 = pk[(size_t)(r + 1) * DM], v1 = pv[(size_t)(r + 1) * DM];
        float k2 = pk[(size_t)(r + 2) * DM], v2 = pv[(size_t)(r + 2) * DM];
        float k3 = pk[(size_t)(r + 3) * DM], v3 = pv[(size_t)(r + 3) * DM];
        s1 += (k0 + k1) + (k2 + k3);
        s2 += (v0 + v1) + (v2 + v3);
    }
    for (; r < R_REL; r++) {
        s1 += pk[(size_t)r * DM];
        s2 += pv[(size_t)r * DM];
    }
    ksum[b * DM + j] = s1;
    vsum[b * DM + j] = s2;
}

// ---------------- merged fused flash attention (doc-doc + rel-cross) ----------------
// blockIdx.x < QT_DOC  : doc mode  Q=dq,  Lq=1024, K/V adds = ksum/vsum, out=psid
// blockIdx.x >= QT_DOC : rel mode  Q=rk,  Lq=97,   out_add = rv,         out=psir
// K/V double-buffered in smem with register-staged global prefetch.
struct AttnSm {
    float Qt[64][68];      // Qt[d][row]
    float Kt[2][64][68];   // Kt[buf][d][key]
    float Vs[2][64][68];   // Vs[buf][key][d]
    float Ps[64][68];      // Ps[row][key]
    float kb[2][64];       // per-key additive bias (SMOOTH or SMOOTH-1e9)
};

__global__ __launch_bounds__(256, 2) void attn_merged(
    const float* __restrict__ dq,    // [B, L_DOC, DM]
    const float* __restrict__ Kd,    // [B, L_DOC, DM]
    const float* __restrict__ Vd,    // [B, L_DOC, DM]
    const float* __restrict__ rkq,   // [B, R_REL, DM] (Q for rel mode)
    const float* __restrict__ rv,    // [B, R_REL, DM] (out_add for rel mode)
    const float* __restrict__ ksum,  // [B, DM]
    const float* __restrict__ vsum,  // [B, DM]
    const int*   __restrict__ mask,  // [B, L_DOC]
    float* __restrict__ psid,        // [B, L_DOC, DM]
    float* __restrict__ psir)        // [B, R_REL, DM]
{
    extern __shared__ char smraw[];
    AttnSm& sm = *reinterpret_cast<AttnSm*>(smraw);

    const bool is_doc = (blockIdx.x < QT_DOC);
    const int qt = is_doc ? blockIdx.x : blockIdx.x - QT_DOC;
    const int h = blockIdx.y, b = blockIdx.z;
    const int tid = threadIdx.x;
    const int tx = tid & 15, ty = tid >> 4;
    const int r0 = ty * 4, c0 = tx * 4;
    const int q0 = qt * 64;

    const float* Q       = is_doc ? dq   : rkq;
    const float* out_add = is_doc ? nullptr : rv;
    float*       Out     = is_doc ? psid : psir;
    const int    Lq      = is_doc ? L_DOC : R_REL;

    // per-thread K/V load coords: d4 is chunk-invariant, j steps by 16
    const int ld_j  = tid >> 4;          // 0..15 (+16 per i)
    const int ld_d4 = (tid & 15) << 2;   // constant per thread

    // fused adds are chunk-invariant; zero in rel mode (unconditional add)
    float4 ka = make_float4(0.f, 0.f, 0.f, 0.f);
    float4 va = make_float4(0.f, 0.f, 0.f, 0.f);
    if (is_doc) {
        ka = *(const float4*)&ksum[b * DM + h * HD + ld_d4];
        va = *(const float4*)&vsum[b * DM + h * HD + ld_d4];
    }

    float4 pk[4], pv[4];
    float  pb = 0.f;

    // ---- prefetch chunk 0 into registers ----
    #pragma unroll
    for (int i = 0; i < 4; i++) {
        size_t gidx = (size_t)(b * L_DOC + ld_j + i * 16) * DM + h * HD + ld_d4;
        pk[i] = *(const float4*)&Kd[gidx];
        pv[i] = *(const float4*)&Vd[gidx];
    }
    if (tid < 64)
        pb = (mask[b * L_DOC + tid] == 0) ? (SMOOTH - 1e9f) : SMOOTH;

    // ---- load Q tile transposed ----
    #pragma unroll
    for (int i = 0; i < 4; i++) {
        int e   = tid + i * 256;
        int row = e >> 4;
        int d4  = (e & 15) << 2;
        int tok = q0 + row;
        float4 v = make_float4(0.f, 0.f, 0.f, 0.f);
        if (tok < Lq)
            v = *(const float4*)&Q[(size_t)(b * Lq + tok) * DM + h * HD + d4];
        sm.Qt[d4 + 0][row] = v.x; sm.Qt[d4 + 1][row] = v.y;
        sm.Qt[d4 + 2][row] = v.z; sm.Qt[d4 + 3][row] = v.w;
    }

    // ---- store chunk 0 to buffer 0 ----
    #pragma unroll
    for (int i = 0; i < 4; i++) {
        int j = ld_j + i * 16;
        sm.Kt[0][ld_d4 + 0][j] = pk[i].x + ka.x;
        sm.Kt[0][ld_d4 + 1][j] = pk[i].y + ka.y;
        sm.Kt[0][ld_d4 + 2][j] = pk[i].z + ka.z;
        sm.Kt[0][ld_d4 + 3][j] = pk[i].w + ka.w;
        float4 vs = make_float4(pv[i].x + va.x, pv[i].y + va.y,
                                pv[i].z + va.z, pv[i].w + va.w);
        *(float4*)&sm.Vs[0][j][ld_d4] = vs;
    }
    if (tid < 64) sm.kb[0][tid] = pb;
    __syncthreads();

    float acc[4][4];
    float m_reg[4], l_reg[4];
    #pragma unroll
    for (int i = 0; i < 4; i++) {
        m_reg[i] = -INFINITY; l_reg[i] = 0.f;
        #pragma unroll
        for (int j = 0; j < 4; j++) acc[i][j] = 0.f;
    }

    for (int t = 0; t < N_CHUNK; t++) {
        const int buf = t & 1;

        // prefetch chunk t+1 into registers (overlaps S-compute + softmax)
        if (t + 1 < N_CHUNK) {
            const int kt = (t + 1) * 64;
            #pragma unroll
            for (int i = 0; i < 4; i++) {
                size_t gidx = (size_t)(b * L_DOC + kt + ld_j + i * 16) * DM + h * HD + ld_d4;
                pk[i] = *(const float4*)&Kd[gidx];
                pv[i] = *(const float4*)&Vd[gidx];
            }
            if (tid < 64)
                pb = (mask[b * L_DOC + kt + tid] == 0) ? (SMOOTH - 1e9f) : SMOOTH;
        }

        // S = Q K^T (4x4 per thread)
        float s[4][4];
        #pragma unroll
        for (int i = 0; i < 4; i++)
            #pragma unroll
            for (int j = 0; j < 4; j++) s[i][j] = 0.f;
        #pragma unroll
        for (int d = 0; d < 64; d++) {
            float4 a  = *(const float4*)&sm.Qt[d][r0];
            float4 bb = *(const float4*)&sm.Kt[buf][d][c0];
            float av[4] = {a.x, a.y, a.z, a.w};
            float bv[4] = {bb.x, bb.y, bb.z, bb.w};
            #pragma unroll
            for (int i = 0; i < 4; i++)
                #pragma unroll
                for (int j = 0; j < 4; j++)
                    s[i][j] += av[i] * bv[j];
        }

        float4 kb4 = *(const float4*)&sm.kb[buf][c0];
        float kb[4] = {kb4.x, kb4.y, kb4.z, kb4.w};

        // scale + bias (mask+smooth folded), row max (shuffle over 16-lane half-warp)
        float mnew[4], f[4];
        #pragma unroll
        for (int i = 0; i < 4; i++) {
            float rm = -INFINITY;
            #pragma unroll
            for (int j = 0; j < 4; j++) {
                float v = fmaf(s[i][j], ATTN_SCALE, kb[j]);
                s[i][j] = v;
                rm = fmaxf(rm, v);
            }
            #pragma unroll
            for (int off = 1; off < 16; off <<= 1)
                rm = fmaxf(rm, __shfl_xor_sync(0xffffffffu, rm, off));
            mnew[i] = fmaxf(m_reg[i], rm);
            f[i] = __expf(m_reg[i] - mnew[i]);   // -inf-finite -> 0 (first chunk)
            m_reg[i] = mnew[i];
        }

        // P = exp(S - m), row sums via shuffle; write P to shared
        #pragma unroll
        for (int i = 0; i < 4; i++) {
            float p0 = __expf(s[i][0] - m_reg[i]);
            float p1 = __expf(s[i][1] - m_reg[i]);
            float p2 = __expf(s[i][2] - m_reg[i]);
            float p3 = __expf(s[i][3] - m_reg[i]);
            float rs = p0 + p1 + p2 + p3;
            #pragma unroll
            for (int off = 1; off < 16; off <<= 1)
                rs += __shfl_xor_sync(0xffffffffu, rs, off);
            l_reg[i] = l_reg[i] * f[i] + rs;
            #pragma unroll
            for (int j = 0; j < 4; j++) acc[i][j] *= f[i];
            *(float4*)&sm.Ps[r0 + i][c0] = make_float4(p0, p1, p2, p3);
        }
        __syncthreads();

        // O += P @ V : keys in groups of 4; P rows read as float4
        #pragma unroll
        for (int j4 = 0; j4 < 64; j4 += 4) {
            float4 p0 = *(const float4*)&sm.Ps[r0 + 0][j4];
            float4 p1 = *(const float4*)&sm.Ps[r0 + 1][j4];
            float4 p2 = *(const float4*)&sm.Ps[r0 + 2][j4];
            float4 p3 = *(const float4*)&sm.Ps[r0 + 3][j4];
            float pr[4][4] = {{p0.x, p0.y, p0.z, p0.w},
                              {p1.x, p1.y, p1.z, p1.w},
                              {p2.x, p2.y, p2.z, p2.w},
                              {p3.x, p3.y, p3.z, p3.w}};
            #pragma unroll
            for (int jj = 0; jj < 4; jj++) {
                float4 vv = *(const float4*)&sm.Vs[buf][j4 + jj][c0];
                float bv[4] = {vv.x, vv.y, vv.z, vv.w};
                #pragma unroll
                for (int i = 0; i < 4; i++) {
                    #pragma unroll
                    for (int c = 0; c < 4; c++)
                        acc[i][c] += pr[i][jj] * bv[c];
                }
            }
        }

        // store prefetched chunk t+1 to the other buffer (read last in t-1, sealed)
        if (t + 1 < N_CHUNK) {
            const int nb = buf ^ 1;
            #pragma unroll
            for (int i = 0; i < 4; i++) {
                int j = ld_j + i * 16;
                sm.Kt[nb][ld_d4 + 0][j] = pk[i].x + ka.x;
                sm.Kt[nb][ld_d4 + 1][j] = pk[i].y + ka.y;
                sm.Kt[nb][ld_d4 + 2][j] = pk[i].z + ka.z;
                sm.Kt[nb][ld_d4 + 3][j] = pk[i].w + ka.w;
                float4 vs = make_float4(pv[i].x + va.x, pv[i].y + va.y,
                                        pv[i].z + va.z, pv[i].w + va.w);
                *(float4*)&sm.Vs[nb][j][ld_d4] = vs;
            }
            if (tid < 64) sm.kb[nb][tid] = pb;
        }
        __syncthreads();
    }

    // epilogue
    #pragma unroll
    for (int i = 0; i < 4; i++) {
        int tok = q0 + r0 + i;
        if (tok >= Lq) continue;
        float inv = 1.0f / l_reg[i];
        size_t oidx = (size_t)(b * Lq + tok) * DM + h * HD + c0;
        float4 o = make_float4(acc[i][0] * inv, acc[i][1] * inv,
                               acc[i][2] * inv, acc[i][3] * inv);
        if (out_add) {
            float4 oa = *(const float4*)&out_add[oidx];
            o.x += oa.x; o.y += oa.y; o.z += oa.z; o.w += oa.w;
        }
        *(float4*)&Out[oidx] = o;
    }
}

// ---------------- merged LayerNorm: rows [0,M_DOC) doc, [M_DOC,M_DOC+M_REL) rel ----------------
// 192 threads: one float4 per thread per array (768 = 192*4). Vectorized LDG/STG.
__global__ __launch_bounds__(192) void ln_merged(
    const float* __restrict__ yd, const float* __restrict__ yr,
    const float* __restrict__ gd, const float* __restrict__ bd,
    const float* __restrict__ gr, const float* __restrict__ br,
    float* __restrict__ out_doc, float* __restrict__ out_rel)
{
    const int rid = blockIdx.x;
    const bool is_doc = (rid < M_DOC);
    const int row = is_doc ? rid : rid - M_DOC;
    const float* y  = is_doc ? yd : yr;
    const float* g  = is_doc ? gd : gr;
    const float* be = is_doc ? bd : br;
    float* out      = is_doc ? out_doc : out_rel;

    const int tid = threadIdx.x;  // 192
    const int lane = tid & 31, wid = tid >> 5;   // 6 warps
    const size_t base = (size_t)row * DM;

    float4 v = *(const float4*)&y[base + tid * 4];
    float s  = (v.x + v.y) + (v.z + v.w);
    float sq = (v.x * v.x + v.y * v.y) + (v.z * v.z + v.w * v.w);

    // intra-warp reduce
    #pragma unroll
    for (int o = 16; o > 0; o >>= 1) {
        s  += __shfl_xor_sync(0xffffffffu, s,  o);
        sq += __shfl_xor_sync(0xffffffffu, sq, o);
    }
    __shared__ float ws[6], wq[6];
    if (lane == 0) { ws[wid] = s; wq[wid] = sq; }
    __syncthreads();
    __shared__ float s_mean, s_rstd;
    if (tid == 0) {
        float ts = 0.f, tq = 0.f;
        #pragma unroll
        for (int w = 0; w < 6; w++) { ts += ws[w]; tq += wq[w]; }
        float m   = ts * (1.0f / DM);
        float var = tq * (1.0f / DM) - m * m;
        s_mean = m;
        s_rstd = rsqrtf(var + LN_EPS);
    }
    __syncthreads();
    float m = s_mean, r = s_rstd;
    float4 gg = *(const float4*)&g[tid * 4];
    float4 bb = *(const float4*)&be[tid * 4];
    float4 o;
    o.x = (v.x - m) * r * gg.x + bb.x;
    o.y = (v.y - m) * r * gg.y + bb.y;
    o.z = (v.z - m) * r * gg.z + bb.z;
    o.w = (v.w - m) * r * gg.w + bb.w;
    *(float4*)&out[base + tid * 4] = o;
}

// ---------------- host ----------------
extern "C" void kernel_launch(void* const* d_in, const int* in_sizes, int n_in,
                              void* d_out, int out_size)
{
    const float* doc    = (const float*)d_in[0];
    const float* rel    = (const float*)d_in[1];
    const int*   mask   = (const int*)  d_in[2];
    const float* wq     = (const float*)d_in[3];
    const float* wk     = (const float*)d_in[4];
    const float* wv     = (const float*)d_in[5];
    const float* wkr    = (const float*)d_in[6];
    const float* wvr    = (const float*)d_in[7];
    const float* fcd    = (const float*)d_in[8];
    const float* fcr    = (const float*)d_in[9];
    const float* lngd   = (const float*)d_in[10];
    const float* lnbd   = (const float*)d_in[11];
    const float* lngr   = (const float*)d_in[12];
    const float* lnbr   = (const float*)d_in[13];

    float* out_doc = (float*)d_out;
    float* out_rel = out_doc + (size_t)M_DOC * DM;

    float *dq, *dk, *dv, *rk, *rv, *ksum, *vsum, *psid, *psir, *yd, *yr;
    cudaGetSymbolAddress((void**)&dq,   g_dq);
    cudaGetSymbolAddress((void**)&dk,   g_dk);
    cudaGetSymbolAddress((void**)&dv,   g_dv);
    cudaGetSymbolAddress((void**)&rk,   g_rk);
    cudaGetSymbolAddress((void**)&rv,   g_rv);
    cudaGetSymbolAddress((void**)&ksum, g_ksum);
    cudaGetSymbolAddress((void**)&vsum, g_vsum);
    cudaGetSymbolAddress((void**)&psid, g_psid);
    cudaGetSymbolAddress((void**)&psir, g_psir);
    cudaGetSymbolAddress((void**)&yd,   g_yd);
    cudaGetSymbolAddress((void**)&yr,   g_yr);

    const int attn_smem = (int)sizeof(AttnSm);
    cudaFuncSetAttribute(attn_merged, cudaFuncAttributeMaxDynamicSharedMemorySize, attn_smem);

    dim3 blk(256);

    // all 5 projections in one launch (z selects {A,W,C,M}); rel tail blocks early-exit
    proj_batched<<<dim3(12, 32, 5), blk>>>(doc, rel, wq, wk, wv, wkr, wvr,
                                           dq, dk, dv, rk, rv);

    // relation sums (parallel over batch x column-chunks)
    relsum_kernel<<<dim3(B_SZ, DM / 128), 128>>>(rk, rv, ksum, vsum);

    // doc-doc + rel-cross attention in one launch (x: 16 doc tiles + 2 rel tiles)
    attn_merged<<<dim3(QT_DOC + QT_REL, NHEAD, B_SZ), blk, attn_smem>>>(
        dq, dk, dv, rk, rv, ksum, vsum, mask, psid, psir);

    // both output FCs (fused residual) in one launch
    fc_batched<<<dim3(12, 32, 2), blk>>>(psid, psir, fcd, fcr, doc, rel, yd, yr);

    // both layernorms in one launch -> outputs (192 threads = 768/4 float4 lanes)
    ln_merged<<<M_DOC + M_REL, 192>>>(yd, yr, lngd, lnbd, lngr, lnbr,
                                      out_doc, out_rel);
}